// round 1
// baseline (speedup 1.0000x reference)
#include <cuda_runtime.h>
#include <cstdint>

#define B_ 8
#define E_ 512
#define L_ 8192
#define KS_ 5
#define LC_ (L_ - KS_ + 1)   // 8188
#define NB3_ 2730            // ceil(LC_/3): number of w=3 blocks

// Scratch (allocation-free rule: __device__ globals)
__device__ float g_y[(size_t)B_ * E_ * L_];   // conv output, zero-padded for t in [LC_, L_)
__device__ float g_s[(size_t)B_ * L_];        // per-position score, zero-padded

// ---------------- packed fp32x2 helpers ----------------
__device__ __forceinline__ unsigned long long pack2(float lo, float hi) {
    unsigned long long r;
    asm("mov.b64 %0, {%1, %2};" : "=l"(r) : "f"(lo), "f"(hi));
    return r;
}
__device__ __forceinline__ void unpack2(unsigned long long v, float& lo, float& hi) {
    asm("mov.b64 {%0, %1}, %2;" : "=f"(lo), "=f"(hi) : "l"(v));
}
__device__ __forceinline__ void fma2(unsigned long long& d, unsigned long long a, unsigned long long b) {
    asm("fma.rn.f32x2 %0, %1, %2, %0;" : "+l"(d) : "l"(a), "l"(b));
}

// ---------------- K1: conv as implicit GEMM ----------------
// Tile: BM=64 t-positions, BN=64 e_out, loop e_in in chunks of 8 (K-chunk = 40).
// Thread (tx,ty): 4 t's (strided 16, coalesced stores) x 4 e's (contiguous, packed FFMA2).
#define BM 64
#define BN 64
#define BKE 8

__global__ __launch_bounds__(256) void conv_kernel(
    const float* __restrict__ x, const float* __restrict__ w, const float* __restrict__ bias)
{
    __shared__ __align__(16) float xs[BKE][BM + KS_ - 1];       // [8][68]
    __shared__ __align__(16) float ws[BKE * KS_][BN];           // [40][64]

    const int b  = blockIdx.z;
    const int t0 = blockIdx.x * BM;
    const int e0 = blockIdx.y * BN;
    const int tid = threadIdx.x;
    const int tx = tid & 15;      // t dim
    const int ty = tid >> 4;      // e dim (4 contiguous e's per thread)

    const float* xb = x + (size_t)b * E_ * L_;

    unsigned long long acc01[4], acc23[4];
#pragma unroll
    for (int i = 0; i < 4; i++) { acc01[i] = 0ull; acc23[i] = 0ull; }

    for (int ei0 = 0; ei0 < E_; ei0 += BKE) {
        // load x tile: 8 rows x 68 cols
        for (int idx = tid; idx < BKE * (BM + KS_ - 1); idx += 256) {
            int r = idx / (BM + KS_ - 1);
            int c = idx - r * (BM + KS_ - 1);
            int t = t0 + c;
            xs[r][c] = (t < L_) ? xb[(size_t)(ei0 + r) * L_ + t] : 0.f;
        }
        // load w tile: each thread reads 10 consecutive floats (2 e_in x 5 taps) for one e_out
        {
            int e = tid & 63;
            int g = tid >> 6;   // 0..3
            const float* wp = w + ((size_t)(e0 + e) * E_ + (ei0 + g * 2)) * KS_;
#pragma unroll
            for (int u = 0; u < 10; u++) {
                int i = g * 2 + u / 5, kk = u % 5;
                ws[i * KS_ + kk][e] = wp[u];
            }
        }
        __syncthreads();

#pragma unroll
        for (int i = 0; i < BKE; i++) {
#pragma unroll
            for (int kk = 0; kk < KS_; kk++) {
                const int k = i * KS_ + kk;
                const unsigned long long* bp =
                    reinterpret_cast<const unsigned long long*>(&ws[k][ty << 2]);
                unsigned long long b01 = bp[0];
                unsigned long long b23 = bp[1];
#pragma unroll
                for (int ii = 0; ii < 4; ii++) {
                    float a = xs[i][tx + 16 * ii + kk];
                    unsigned long long aa = pack2(a, a);
                    fma2(acc01[ii], aa, b01);
                    fma2(acc23[ii], aa, b23);
                }
            }
        }
        __syncthreads();
    }

    // epilogue: add bias; zero-fill t >= LC_ so downstream padding semantics are free
    float bv[4];
#pragma unroll
    for (int jj = 0; jj < 4; jj++) bv[jj] = bias[e0 + (ty << 2) + jj];

#pragma unroll
    for (int ii = 0; ii < 4; ii++) {
        int t = t0 + tx + 16 * ii;
        float v0, v1, v2, v3;
        unpack2(acc01[ii], v0, v1);
        unpack2(acc23[ii], v2, v3);
        float vals[4] = {v0 + bv[0], v1 + bv[1], v2 + bv[2], v3 + bv[3]};
        bool ok = (t < LC_);
#pragma unroll
        for (int jj = 0; jj < 4; jj++) {
            int e = e0 + (ty << 2) + jj;
            g_y[((size_t)b * E_ + e) * L_ + t] = ok ? vals[jj] : 0.f;
        }
    }
}

// ---------------- K2: per-position scores s[b,t] = <y[b,:,t], score_w> ----------------
__global__ __launch_bounds__(256) void score_kernel(const float* __restrict__ sw) {
    __shared__ float swv[E_];
    const int b = blockIdx.y;
    const int t = blockIdx.x * 256 + threadIdx.x;
    for (int i = threadIdx.x; i < E_; i += 256) swv[i] = sw[i];
    __syncthreads();
    const float* yb = g_y + (size_t)b * E_ * L_;
    float acc = 0.f;
#pragma unroll 8
    for (int e = 0; e < E_; e++) acc += yb[(size_t)e * L_ + t] * swv[e];
    g_s[(size_t)b * L_ + t] = acc;   // t >= LC_ rows are zero -> acc == 0 (matches padding)
}

// ---------------- K3: softmax mix over widths {1,2,3} + downsample-by-2 ----------------
#define OT 32   // output positions per block
__global__ __launch_bounds__(256) void epilogue_kernel(float* __restrict__ out) {
    __shared__ float att[2 * OT][3];
    const int b  = blockIdx.y;
    const int o0 = blockIdx.x * OT;
    const int tid = threadIdx.x;
    const float* sb = g_s + (size_t)b * L_;

    if (tid < 2 * OT) {
        int l = 2 * o0 + tid;
        float c1 = sb[l];
        int n2 = l >> 1;
        float c2 = 0.5f * (sb[2 * n2] + sb[2 * n2 + 1]);
        int n3 = l / 3;
        float c3 = (n3 < NB3_) ? (sb[3 * n3] + sb[3 * n3 + 1] + sb[3 * n3 + 2]) * (1.f / 3.f) : 0.f;
        float m = fmaxf(c1, fmaxf(c2, c3));
        float a1 = __expf(c1 - m), a2 = __expf(c2 - m), a3 = __expf(c3 - m);
        float inv = 1.f / (a1 + a2 + a3);
        att[tid][0] = a1 * inv;
        att[tid][1] = a2 * inv;
        att[tid][2] = a3 * inv;
    }
    __syncthreads();

    const float* yb = g_y + (size_t)b * E_ * L_;
    const int ol = tid & (OT - 1);
    const int o  = o0 + ol;
    const int l0 = 2 * o, l1 = l0 + 1;
    const int n3a = l0 / 3, n3b = l1 / 3;
    const bool ok3a = (n3a < NB3_), ok3b = (n3b < NB3_);
    const float w10 = att[2 * ol][0],     w20 = att[2 * ol][1],     w30 = att[2 * ol][2];
    const float w11 = att[2 * ol + 1][0], w21 = att[2 * ol + 1][1], w31 = att[2 * ol + 1][2];

    for (int e = tid / OT; e < E_; e += 256 / OT) {
        const float* yr = yb + (size_t)e * L_;
        float ya = yr[l0], ybv = yr[l1];
        float v2 = 0.5f * (ya + ybv);                       // w=2: same block for l0 and l1
        float v3a = ok3a ? (yr[3 * n3a] + yr[3 * n3a + 1] + yr[3 * n3a + 2]) * (1.f / 3.f) : 0.f;
        float v3b = (n3b == n3a) ? v3a
                  : (ok3b ? (yr[3 * n3b] + yr[3 * n3b + 1] + yr[3 * n3b + 2]) * (1.f / 3.f) : 0.f);
        float out0 = ya  * w10 + v2 * w20 + v3a * w30;
        float out1 = ybv * w11 + v2 * w21 + v3b * w31;
        out[((size_t)b * E_ + e) * (L_ / 2) + o] = 0.5f * (out0 + out1);
    }
}

extern "C" void kernel_launch(void* const* d_in, const int* in_sizes, int n_in,
                              void* d_out, int out_size) {
    const float* x      = (const float*)d_in[0];
    const float* conv_w = (const float*)d_in[1];
    const float* conv_b = (const float*)d_in[2];
    const float* score_w = (const float*)d_in[3];
    float* out = (float*)d_out;

    dim3 g1(L_ / BM, E_ / BN, B_);          // 128 x 8 x 8
    conv_kernel<<<g1, 256>>>(x, conv_w, conv_b);

    dim3 g2(L_ / 256, B_);
    score_kernel<<<g2, 256>>>(score_w);

    dim3 g3((L_ / 2) / OT, B_);
    epilogue_kernel<<<g3, 256>>>(out);
}